// round 1
// baseline (speedup 1.0000x reference)
#include <cuda_runtime.h>
#include <math.h>

#define N_NODES 20000
#define N_EDGES 320000
#define HDIM    128
#define INDIM   256

// scatter accumulator scratch (10.24 MB) — static __device__ per allocation rules
__device__ float g_dh[N_NODES * HDIM];

__device__ __forceinline__ float gelu_f(float x) { return x * normcdff(x); }  // exact erf GELU

__device__ __forceinline__ void red_add_v4(float* p, float4 v) {
    asm volatile("red.global.add.v4.f32 [%0], {%1, %2, %3, %4};"
                 :: "l"(p), "f"(v.x), "f"(v.y), "f"(v.z), "f"(v.w) : "memory");
}

__global__ void zero_dh_kernel() {
    int i = blockIdx.x * blockDim.x + threadIdx.x;
    ((float4*)g_dh)[i] = make_float4(0.f, 0.f, 0.f, 0.f);
}

// ---------------------------------------------------------------------------
// Edge kernel: 64 edges per block, 256 threads.
// thread tile: rows = ty + 16*r (r=0..3), cols = 4*tx + 64*c (c=0..1)
// smem: sA[64][32] | sW[32][128] | sH1[64][128] | sH2[64][128]  = 88 KB dynamic
// ---------------------------------------------------------------------------

// GEMM over K=128 with A already resident in smem (row stride 128)
__device__ __forceinline__ void gemm_k128(const float* __restrict__ Wg,
                                          const float* sSrc, float* sW,
                                          float acc[4][8], int tx, int ty, int tid)
{
#pragma unroll 1
    for (int kc = 0; kc < 4; kc++) {
        const float4* wp = (const float4*)(Wg + kc * 32 * HDIM);
#pragma unroll
        for (int i = 0; i < 4; i++)
            ((float4*)sW)[tid + i * 256] = wp[tid + i * 256];
        __syncthreads();
#pragma unroll 8
        for (int k = 0; k < 32; k++) {
            float4 u = ((float4*)sW)[k * 32 + tx];
            float4 v = ((float4*)sW)[k * 32 + tx + 16];
#pragma unroll
            for (int r = 0; r < 4; r++) {
                float a = sSrc[(ty + 16 * r) * HDIM + kc * 32 + k];
                acc[r][0] += a * u.x; acc[r][1] += a * u.y;
                acc[r][2] += a * u.z; acc[r][3] += a * u.w;
                acc[r][4] += a * v.x; acc[r][5] += a * v.y;
                acc[r][6] += a * v.z; acc[r][7] += a * v.w;
            }
        }
        __syncthreads();
    }
}

__global__ void __launch_bounds__(256)
edge_mlp_kernel(const float* __restrict__ hE, const int* __restrict__ eidx,
                const float* __restrict__ W1, const float* __restrict__ B1,
                const float* __restrict__ W2, const float* __restrict__ B2,
                const float* __restrict__ W3, const float* __restrict__ B3)
{
    extern __shared__ float sm[];
    float* sA  = sm;                 // 2048 floats
    float* sW  = sm + 2048;          // 4096 floats
    float* sH1 = sm + 2048 + 4096;   // 8192 floats
    float* sH2 = sH1 + 8192;         // 8192 floats

    const int tid = threadIdx.x;
    const int tx  = tid & 15;
    const int ty  = tid >> 4;
    const int e0  = blockIdx.x * 64;

    float acc[4][8];
#pragma unroll
    for (int r = 0; r < 4; r++)
#pragma unroll
        for (int i = 0; i < 8; i++) acc[r][i] = 0.f;

    // ---- GEMM1: [64 x 256] @ [256 x 128] ----
#pragma unroll 1
    for (int kc = 0; kc < 8; kc++) {
#pragma unroll
        for (int i = 0; i < 2; i++) {
            int idx = tid + i * 256;                // 0..511 float4
            int row = idx >> 3, c4 = idx & 7;
            ((float4*)sA)[idx] =
                *(const float4*)(hE + (size_t)(e0 + row) * INDIM + kc * 32 + c4 * 4);
        }
        const float4* wp = (const float4*)(W1 + kc * 32 * HDIM);
#pragma unroll
        for (int i = 0; i < 4; i++)
            ((float4*)sW)[tid + i * 256] = wp[tid + i * 256];
        __syncthreads();
#pragma unroll 8
        for (int k = 0; k < 32; k++) {
            float4 u = ((float4*)sW)[k * 32 + tx];
            float4 v = ((float4*)sW)[k * 32 + tx + 16];
#pragma unroll
            for (int r = 0; r < 4; r++) {
                float a = sA[(ty + 16 * r) * 32 + k];
                acc[r][0] += a * u.x; acc[r][1] += a * u.y;
                acc[r][2] += a * u.z; acc[r][3] += a * u.w;
                acc[r][4] += a * v.x; acc[r][5] += a * v.y;
                acc[r][6] += a * v.z; acc[r][7] += a * v.w;
            }
        }
        __syncthreads();
    }
    // bias + gelu -> sH1
    {
        float4 c0 = *(const float4*)(B1 + 4 * tx);
        float4 c1 = *(const float4*)(B1 + 64 + 4 * tx);
#pragma unroll
        for (int r = 0; r < 4; r++) {
            int row = ty + 16 * r;
            float4 v0, v1;
            v0.x = gelu_f(acc[r][0] + c0.x); v0.y = gelu_f(acc[r][1] + c0.y);
            v0.z = gelu_f(acc[r][2] + c0.z); v0.w = gelu_f(acc[r][3] + c0.w);
            v1.x = gelu_f(acc[r][4] + c1.x); v1.y = gelu_f(acc[r][5] + c1.y);
            v1.z = gelu_f(acc[r][6] + c1.z); v1.w = gelu_f(acc[r][7] + c1.w);
            *(float4*)(sH1 + row * HDIM + 4 * tx)      = v0;
            *(float4*)(sH1 + row * HDIM + 64 + 4 * tx) = v1;
        }
    }
    __syncthreads();

    // ---- GEMM2: gelu(sH1 @ W2 + B2) -> sH2 ----
#pragma unroll
    for (int r = 0; r < 4; r++)
#pragma unroll
        for (int i = 0; i < 8; i++) acc[r][i] = 0.f;
    gemm_k128(W2, sH1, sW, acc, tx, ty, tid);
    {
        float4 c0 = *(const float4*)(B2 + 4 * tx);
        float4 c1 = *(const float4*)(B2 + 64 + 4 * tx);
#pragma unroll
        for (int r = 0; r < 4; r++) {
            int row = ty + 16 * r;
            float4 v0, v1;
            v0.x = gelu_f(acc[r][0] + c0.x); v0.y = gelu_f(acc[r][1] + c0.y);
            v0.z = gelu_f(acc[r][2] + c0.z); v0.w = gelu_f(acc[r][3] + c0.w);
            v1.x = gelu_f(acc[r][4] + c1.x); v1.y = gelu_f(acc[r][5] + c1.y);
            v1.z = gelu_f(acc[r][6] + c1.z); v1.w = gelu_f(acc[r][7] + c1.w);
            *(float4*)(sH2 + row * HDIM + 4 * tx)      = v0;
            *(float4*)(sH2 + row * HDIM + 64 + 4 * tx) = v1;
        }
    }
    __syncthreads();

    // ---- GEMM3: sH2 @ W3 + B3, scale 1/30, scatter ----
#pragma unroll
    for (int r = 0; r < 4; r++)
#pragma unroll
        for (int i = 0; i < 8; i++) acc[r][i] = 0.f;
    gemm_k128(W3, sH2, sW, acc, tx, ty, tid);
    {
        const float inv = 1.0f / 30.0f;
        float4 c0 = *(const float4*)(B3 + 4 * tx);
        float4 c1 = *(const float4*)(B3 + 64 + 4 * tx);
#pragma unroll
        for (int r = 0; r < 4; r++) {
            int row = ty + 16 * r;
            int s = eidx[e0 + row];  // edge_idx[0][e] = src
            float* dst = g_dh + (size_t)s * HDIM;
            float4 v0 = make_float4((acc[r][0] + c0.x) * inv, (acc[r][1] + c0.y) * inv,
                                    (acc[r][2] + c0.z) * inv, (acc[r][3] + c0.w) * inv);
            float4 v1 = make_float4((acc[r][4] + c1.x) * inv, (acc[r][5] + c1.y) * inv,
                                    (acc[r][6] + c1.z) * inv, (acc[r][7] + c1.w) * inv);
            red_add_v4(dst + 4 * tx, v0);
            red_add_v4(dst + 64 + 4 * tx, v1);
        }
    }
}

// ---------------------------------------------------------------------------
// Node kernel: 32 nodes per block, 256 threads (8 warps).
// warp handles rows {wid, wid+8, wid+16, wid+24}; lane handles cols 4*lane..+3
// LN1 -> FFN (128->512 gelu ->128) -> residual -> LN2, all fused.
// ---------------------------------------------------------------------------
__global__ void __launch_bounds__(256)
node_kernel(const float* __restrict__ hV,
            const float* __restrict__ n1g, const float* __restrict__ n1b,
            const float* __restrict__ D1,  const float* __restrict__ D1b,
            const float* __restrict__ D2,  const float* __restrict__ D2b,
            const float* __restrict__ n2g, const float* __restrict__ n2b,
            float* __restrict__ out)
{
    __shared__ float sX[32 * 128];
    __shared__ float sT[32 * 128];
    __shared__ float sW[32 * 128];

    const int tid  = threadIdx.x;
    const int lane = tid & 31;
    const int wid  = tid >> 5;
    const int n0   = blockIdx.x * 32;
    const int col  = 4 * lane;

    // ---- LN1(h_V + dh/30) -> sX ----
    {
        float4 g1 = *(const float4*)(n1g + col);
        float4 b1 = *(const float4*)(n1b + col);
#pragma unroll
        for (int r = 0; r < 4; r++) {
            int row = wid + 8 * r;
            int n = n0 + row;
            float4 hv = *(const float4*)(hV + (size_t)n * HDIM + col);
            float4 dh = *(const float4*)(g_dh + (size_t)n * HDIM + col);
            float4 z;
            z.x = hv.x + dh.x; z.y = hv.y + dh.y; z.z = hv.z + dh.z; z.w = hv.w + dh.w;
            float s = z.x + z.y + z.z + z.w;
            float q = z.x * z.x + z.y * z.y + z.z * z.z + z.w * z.w;
#pragma unroll
            for (int o = 16; o > 0; o >>= 1) {
                s += __shfl_xor_sync(0xffffffffu, s, o);
                q += __shfl_xor_sync(0xffffffffu, q, o);
            }
            float m = s * (1.f / 128.f);
            float var = q * (1.f / 128.f) - m * m;
            float rstd = rsqrtf(var + 1e-5f);
            float4 x;
            x.x = (z.x - m) * rstd * g1.x + b1.x;
            x.y = (z.y - m) * rstd * g1.y + b1.y;
            x.z = (z.z - m) * rstd * g1.z + b1.z;
            x.w = (z.w - m) * rstd * g1.w + b1.w;
            *(float4*)(sX + row * HDIM + col) = x;
        }
    }
    __syncthreads();

    // ---- FFN: acc2 = gelu(sX @ D1 + D1b) @ D2, processed in 4 N-chunks ----
    float acc2[4][4];
#pragma unroll
    for (int r = 0; r < 4; r++)
#pragma unroll
        for (int i = 0; i < 4; i++) acc2[r][i] = 0.f;

#pragma unroll 1
    for (int nc = 0; nc < 4; nc++) {
        float acc1[4][4];
#pragma unroll
        for (int r = 0; r < 4; r++)
#pragma unroll
            for (int i = 0; i < 4; i++) acc1[r][i] = 0.f;

#pragma unroll 1
        for (int kc = 0; kc < 4; kc++) {
#pragma unroll
            for (int i = 0; i < 4; i++) {
                int idx = tid + i * 256;
                int row = idx >> 5, c4 = idx & 31;
                ((float4*)sW)[idx] =
                    *(const float4*)(D1 + (size_t)(kc * 32 + row) * 512 + nc * 128 + 4 * c4);
            }
            __syncthreads();
#pragma unroll 8
            for (int k = 0; k < 32; k++) {
                float4 b = ((float4*)sW)[k * 32 + lane];
#pragma unroll
                for (int r = 0; r < 4; r++) {
                    float a = sX[(wid + 8 * r) * HDIM + kc * 32 + k];
                    acc1[r][0] += a * b.x; acc1[r][1] += a * b.y;
                    acc1[r][2] += a * b.z; acc1[r][3] += a * b.w;
                }
            }
            __syncthreads();
        }
        // gelu + bias -> sT
        {
            float4 db = *(const float4*)(D1b + nc * 128 + col);
#pragma unroll
            for (int r = 0; r < 4; r++) {
                int row = wid + 8 * r;
                float4 t;
                t.x = gelu_f(acc1[r][0] + db.x);
                t.y = gelu_f(acc1[r][1] + db.y);
                t.z = gelu_f(acc1[r][2] + db.z);
                t.w = gelu_f(acc1[r][3] + db.w);
                *(float4*)(sT + row * HDIM + col) = t;
            }
        }
        __syncthreads();
        // acc2 += sT @ D2[nc*128 : nc*128+128, :]
#pragma unroll 1
        for (int kc = 0; kc < 4; kc++) {
#pragma unroll
            for (int i = 0; i < 4; i++) {
                int idx = tid + i * 256;
                int row = idx >> 5, c4 = idx & 31;
                ((float4*)sW)[idx] =
                    *(const float4*)(D2 + (size_t)(nc * 128 + kc * 32 + row) * 128 + 4 * c4);
            }
            __syncthreads();
#pragma unroll 8
            for (int k = 0; k < 32; k++) {
                float4 b = ((float4*)sW)[k * 32 + lane];
#pragma unroll
                for (int r = 0; r < 4; r++) {
                    float a = sT[(wid + 8 * r) * HDIM + kc * 32 + k];
                    acc2[r][0] += a * b.x; acc2[r][1] += a * b.y;
                    acc2[r][2] += a * b.z; acc2[r][3] += a * b.w;
                }
            }
            __syncthreads();
        }
    }

    // ---- residual + bias + LN2 -> out ----
    {
        float4 g2  = *(const float4*)(n2g + col);
        float4 b2  = *(const float4*)(n2b + col);
        float4 db2 = *(const float4*)(D2b + col);
#pragma unroll
        for (int r = 0; r < 4; r++) {
            int row = wid + 8 * r;
            float4 x = *(float4*)(sX + row * HDIM + col);
            float4 z;
            z.x = x.x + acc2[r][0] + db2.x;
            z.y = x.y + acc2[r][1] + db2.y;
            z.z = x.z + acc2[r][2] + db2.z;
            z.w = x.w + acc2[r][3] + db2.w;
            float s = z.x + z.y + z.z + z.w;
            float q = z.x * z.x + z.y * z.y + z.z * z.z + z.w * z.w;
#pragma unroll
            for (int o = 16; o > 0; o >>= 1) {
                s += __shfl_xor_sync(0xffffffffu, s, o);
                q += __shfl_xor_sync(0xffffffffu, q, o);
            }
            float m = s * (1.f / 128.f);
            float var = q * (1.f / 128.f) - m * m;
            float rstd = rsqrtf(var + 1e-5f);
            float4 y;
            y.x = (z.x - m) * rstd * g2.x + b2.x;
            y.y = (z.y - m) * rstd * g2.y + b2.y;
            y.z = (z.z - m) * rstd * g2.z + b2.z;
            y.w = (z.w - m) * rstd * g2.w + b2.w;
            *(float4*)(out + (size_t)(n0 + row) * HDIM + col) = y;
        }
    }
}

// NOTE: messages are pre-scaled by 1/30 inside edge kernel; LN1 adds dh directly.
// To keep exact parity with reference (sum then /30 is linear), scaling inside
// the edge kernel epilogue is equivalent.

extern "C" void kernel_launch(void* const* d_in, const int* in_sizes, int n_in,
                              void* d_out, int out_size)
{
    const float* hV  = (const float*)d_in[0];
    const float* hE  = (const float*)d_in[1];
    const int* eidx  = (const int*)d_in[2];
    const float* W1  = (const float*)d_in[3];
    const float* B1  = (const float*)d_in[4];
    const float* W2  = (const float*)d_in[5];
    const float* B2  = (const float*)d_in[6];
    const float* W3  = (const float*)d_in[7];
    const float* B3  = (const float*)d_in[8];
    const float* n1g = (const float*)d_in[9];
    const float* n1b = (const float*)d_in[10];
    const float* D1  = (const float*)d_in[11];
    const float* D1b = (const float*)d_in[12];
    const float* D2  = (const float*)d_in[13];
    const float* D2b = (const float*)d_in[14];
    const float* n2g = (const float*)d_in[15];
    const float* n2b = (const float*)d_in[16];
    float* out = (float*)d_out;

    const int edge_smem = (2048 + 4096 + 8192 + 8192) * (int)sizeof(float);  // 88 KB
    cudaFuncSetAttribute(edge_mlp_kernel,
                         cudaFuncAttributeMaxDynamicSharedMemorySize, edge_smem);

    zero_dh_kernel<<<(N_NODES * HDIM / 4) / 256, 256>>>();
    edge_mlp_kernel<<<N_EDGES / 64, 256, edge_smem>>>(hE, eidx, W1, B1, W2, B2, W3, B3);
    node_kernel<<<N_NODES / 32, 256>>>(hV, n1g, n1b, D1, D1b, D2, D2b, n2g, n2b, out);
}

// round 4
// speedup vs baseline: 1.2434x; 1.2434x over previous
#include <cuda_runtime.h>
#include <cuda_bf16.h>
#include <math.h>
#include <stdint.h>

#define N_NODES 20000
#define N_EDGES 320000
#define HDIM    128
#define INDIM   256

// ---------------- device scratch (no allocations allowed) ----------------
__device__ float g_dh[N_NODES * HDIM];
__device__ __align__(16) __nv_bfloat16 g_W1t[2][HDIM][INDIM];  // [hi/lo][n][k]
__device__ __align__(16) __nv_bfloat16 g_W2t[2][HDIM][HDIM];
__device__ __align__(16) __nv_bfloat16 g_W3t[2][HDIM][HDIM];

// ---------------- helpers ----------------
__device__ __forceinline__ float gelu_f(float x) { return x * normcdff(x); }

__device__ __forceinline__ uint32_t smem_u32(const void* p) {
    uint32_t a;
    asm("{ .reg .u64 t; cvta.to.shared.u64 t, %1; cvt.u32.u64 %0, t; }" : "=r"(a) : "l"(p));
    return a;
}

__device__ __forceinline__ void split_pair(float x0, float x1, uint32_t& hp, uint32_t& lp) {
    __nv_bfloat16 h0 = __float2bfloat16(x0), h1 = __float2bfloat16(x1);
    __nv_bfloat16 l0 = __float2bfloat16(x0 - __bfloat162float(h0));
    __nv_bfloat16 l1 = __float2bfloat16(x1 - __bfloat162float(h1));
    hp = (uint32_t)__bfloat16_as_ushort(h0) | ((uint32_t)__bfloat16_as_ushort(h1) << 16);
    lp = (uint32_t)__bfloat16_as_ushort(l0) | ((uint32_t)__bfloat16_as_ushort(l1) << 16);
}

__device__ __forceinline__ void red_add_v2(float* p, float x, float y) {
    asm volatile("red.global.add.v2.f32 [%0], {%1, %2};"
                 :: "l"(p), "f"(x), "f"(y) : "memory");
}

__device__ __forceinline__ void ldsm4(uint32_t addr, uint32_t r[4]) {
    asm volatile("ldmatrix.sync.aligned.m8n8.x4.shared.b16 {%0,%1,%2,%3}, [%4];"
                 : "=r"(r[0]), "=r"(r[1]), "=r"(r[2]), "=r"(r[3]) : "r"(addr));
}

__device__ __forceinline__ void mma16816(float c[4], const uint32_t a[4],
                                         uint32_t b0, uint32_t b1) {
    asm volatile("mma.sync.aligned.m16n8k16.row.col.f32.bf16.bf16.f32 "
                 "{%0,%1,%2,%3}, {%4,%5,%6,%7}, {%8,%9}, {%0,%1,%2,%3};"
                 : "+f"(c[0]), "+f"(c[1]), "+f"(c[2]), "+f"(c[3])
                 : "r"(a[0]), "r"(a[1]), "r"(a[2]), "r"(a[3]), "r"(b0), "r"(b1));
}

// ---------------- misc kernels ----------------
__global__ void zero_dh_kernel() {
    int i = blockIdx.x * blockDim.x + threadIdx.x;
    ((float4*)g_dh)[i] = make_float4(0.f, 0.f, 0.f, 0.f);
}

// weights -> transposed [n][k] bf16 hi/lo planes
// FIXED partition: W1 = 128*256 = 32768, W2 = W3 = 128*128 = 16384; total 65536.
__global__ void prep_weights(const float* __restrict__ W1, const float* __restrict__ W2,
                             const float* __restrict__ W3) {
    int idx = blockIdx.x * 256 + threadIdx.x;
    float w; __nv_bfloat16 *ph, *pl;
    if (idx < 32768) {
        int n = idx >> 8, k = idx & 255;        // n in [0,128), k in [0,256)
        w = W1[k * HDIM + n];
        ph = &g_W1t[0][n][k]; pl = &g_W1t[1][n][k];
    } else if (idx < 49152) {
        int i = idx - 32768; int n = i >> 7, k = i & 127;
        w = W2[k * HDIM + n];
        ph = &g_W2t[0][n][k]; pl = &g_W2t[1][n][k];
    } else {
        int i = idx - 49152; int n = i >> 7, k = i & 127;
        w = W3[k * HDIM + n];
        ph = &g_W3t[0][n][k]; pl = &g_W3t[1][n][k];
    }
    __nv_bfloat16 h = __float2bfloat16(w);
    *ph = h;
    *pl = __float2bfloat16(w - __bfloat162float(h));
}

// ---------------- edge kernel (mma.sync bf16 hi/lo) ----------------
// smem rows padded: 72 bf16 (144 B) per row of a 64-col chunk tile.
#define MSTRIDE 144
#define TILE_B  (128 * MSTRIDE)     // 18432 B
// layout: Ah0 | Ah1 | Al0 | Al1 | Bh | Bl
#define OFF_AH0 0
#define OFF_AH1 (TILE_B)
#define OFF_AL0 (2 * TILE_B)
#define OFF_AL1 (3 * TILE_B)
#define OFF_BH  (4 * TILE_B)
#define OFF_BL  (5 * TILE_B)
#define EDGE_SMEM (6 * TILE_B)      // 110592 B

static __device__ __forceinline__ void loadA_hE(char* th, char* tl, const float* __restrict__ hE,
                                                int e0, int c, int tid) {
#pragma unroll
    for (int it = 0; it < 8; it++) {
        int idx = tid + it * 256;            // 2048 float4 = 128 rows x 16
        int row = idx >> 4, c4 = idx & 15;
        float4 v = *(const float4*)(hE + (size_t)(e0 + row) * INDIM + c * 64 + c4 * 4);
        uint32_t h01, l01, h23, l23;
        split_pair(v.x, v.y, h01, l01);
        split_pair(v.z, v.w, h23, l23);
        int off = row * MSTRIDE + c4 * 8;
        *(uint2*)(th + off) = make_uint2(h01, h23);
        *(uint2*)(tl + off) = make_uint2(l01, l23);
    }
}

static __device__ __forceinline__ void loadB(char* th, char* tl,
                                             const __nv_bfloat16* __restrict__ Wh,
                                             const __nv_bfloat16* __restrict__ Wl,
                                             int K, int c, int tid) {
#pragma unroll
    for (int it = 0; it < 8; it++) {
        int idx = tid + it * 256;            // 2048 uint2 = 128 rows x 16
        int row = idx >> 4, u = idx & 15;
        size_t so = (size_t)row * K + c * 64 + u * 4;
        int off = row * MSTRIDE + u * 8;
        *(uint2*)(th + off) = *(const uint2*)(Wh + so);
        *(uint2*)(tl + off) = *(const uint2*)(Wl + so);
    }
}

// one 64-K chunk: acc += Ah*Bh + Ah*Bl + Al*Bh
static __device__ __forceinline__ void mma_chunk(float acc[2][8][4],
                                                 uint32_t Ah, uint32_t Al,
                                                 uint32_t Bh, uint32_t Bl,
                                                 int m0, int n0, int lane) {
    const int arow = lane & 15;
    const int asel = (lane >> 4) * 16;                      // bytes: +8 cols
    const int brow = (lane & 7) + ((lane >> 4) & 1) * 8;    // row within nt-pair
    const int bksel = ((lane >> 3) & 1) * 16;               // bytes: +8 k
#pragma unroll
    for (int ks = 0; ks < 4; ks++) {
        uint32_t ah[2][4], al[2][4];
#pragma unroll
        for (int mt = 0; mt < 2; mt++) {
            uint32_t off = (uint32_t)(m0 + mt * 16 + arow) * MSTRIDE + ks * 32 + asel;
            ldsm4(Ah + off, ah[mt]);
            ldsm4(Al + off, al[mt]);
        }
        uint32_t bh[8][2], bl[8][2];
#pragma unroll
        for (int np = 0; np < 4; np++) {
            uint32_t r[4];
            uint32_t off = (uint32_t)(n0 + np * 16 + brow) * MSTRIDE + ks * 32 + bksel;
            ldsm4(Bh + off, r);
            bh[np * 2][0] = r[0]; bh[np * 2][1] = r[1];
            bh[np * 2 + 1][0] = r[2]; bh[np * 2 + 1][1] = r[3];
            ldsm4(Bl + off, r);
            bl[np * 2][0] = r[0]; bl[np * 2][1] = r[1];
            bl[np * 2 + 1][0] = r[2]; bl[np * 2 + 1][1] = r[3];
        }
#pragma unroll
        for (int mt = 0; mt < 2; mt++)
#pragma unroll
            for (int nt = 0; nt < 8; nt++)
                mma16816(acc[mt][nt], ah[mt], bh[nt][0], bh[nt][1]);
#pragma unroll
        for (int mt = 0; mt < 2; mt++)
#pragma unroll
            for (int nt = 0; nt < 8; nt++)
                mma16816(acc[mt][nt], ah[mt], bl[nt][0], bl[nt][1]);
#pragma unroll
        for (int mt = 0; mt < 2; mt++)
#pragma unroll
            for (int nt = 0; nt < 8; nt++)
                mma16816(acc[mt][nt], al[mt], bh[nt][0], bh[nt][1]);
    }
}

static __device__ __forceinline__ void zero_acc(float acc[2][8][4]) {
#pragma unroll
    for (int mt = 0; mt < 2; mt++)
#pragma unroll
        for (int nt = 0; nt < 8; nt++)
#pragma unroll
            for (int i = 0; i < 4; i++) acc[mt][nt][i] = 0.f;
}

// epilogue: gelu(acc + bias) -> bf16 hi/lo written into A chunk tile (wid>>2)
static __device__ __forceinline__ void epi_act(float acc[2][8][4], const float* __restrict__ bias,
                                               char* sb, int wid, int lane, int m0, int n0) {
    char* th = sb + OFF_AH0 + (wid >> 2) * TILE_B;
    char* tl = sb + OFF_AL0 + (wid >> 2) * TILE_B;
    const int g = lane >> 2, t = lane & 3;
#pragma unroll
    for (int mt = 0; mt < 2; mt++) {
        int r0 = m0 + mt * 16 + g;
#pragma unroll
        for (int nt = 0; nt < 8; nt++) {
            int col = nt * 8 + 2 * t;                  // 0..63 within warp half
            float b0 = __ldg(&bias[n0 + col]);
            float b1 = __ldg(&bias[n0 + col + 1]);
            float x0 = gelu_f(acc[mt][nt][0] + b0);
            float x1 = gelu_f(acc[mt][nt][1] + b1);
            float x2 = gelu_f(acc[mt][nt][2] + b0);
            float x3 = gelu_f(acc[mt][nt][3] + b1);
            uint32_t hp, lp;
            split_pair(x0, x1, hp, lp);
            int off0 = r0 * MSTRIDE + col * 2;
            *(uint32_t*)(th + off0) = hp;
            *(uint32_t*)(tl + off0) = lp;
            split_pair(x2, x3, hp, lp);
            int off1 = (r0 + 8) * MSTRIDE + col * 2;
            *(uint32_t*)(th + off1) = hp;
            *(uint32_t*)(tl + off1) = lp;
        }
    }
}

static __device__ __forceinline__ void epi_scatter(float acc[2][8][4], const float* __restrict__ bias,
                                                   const int* __restrict__ eidx, int e0,
                                                   int lane, int m0, int n0) {
    const int g = lane >> 2, t = lane & 3;
    const float inv = 1.0f / 30.0f;
#pragma unroll
    for (int mt = 0; mt < 2; mt++) {
        int r0 = m0 + mt * 16 + g;
        int s0 = eidx[e0 + r0];
        int s1 = eidx[e0 + r0 + 8];
        float* d0 = g_dh + (size_t)s0 * HDIM;
        float* d1 = g_dh + (size_t)s1 * HDIM;
#pragma unroll
        for (int nt = 0; nt < 8; nt++) {
            int col = n0 + nt * 8 + 2 * t;
            float b0 = __ldg(&bias[col]);
            float b1 = __ldg(&bias[col + 1]);
            red_add_v2(d0 + col, (acc[mt][nt][0] + b0) * inv, (acc[mt][nt][1] + b1) * inv);
            red_add_v2(d1 + col, (acc[mt][nt][2] + b0) * inv, (acc[mt][nt][3] + b1) * inv);
        }
    }
}

__global__ void __launch_bounds__(256, 1)
edge_mma_kernel(const float* __restrict__ hE, const int* __restrict__ eidx,
                const float* __restrict__ B1, const float* __restrict__ B2,
                const float* __restrict__ B3)
{
    extern __shared__ char sb[];
    const uint32_t ub = smem_u32(sb);

    const int tid = threadIdx.x, lane = tid & 31, wid = tid >> 5;
    const int m0 = (wid & 3) * 32;
    const int n0 = (wid >> 2) * 64;
    const int e0 = blockIdx.x * 128;

    float acc[2][8][4];
    zero_acc(acc);

    // ---- GEMM1: hE[128x256] @ W1 ----
    for (int c = 0; c < 4; c++) {
        loadB(sb + OFF_BH, sb + OFF_BL, &g_W1t[0][0][0], &g_W1t[1][0][0], INDIM, c, tid);
        loadA_hE(sb + OFF_AH0 + (c & 1) * TILE_B, sb + OFF_AL0 + (c & 1) * TILE_B, hE, e0, c, tid);
        __syncthreads();
        mma_chunk(acc, ub + OFF_AH0 + (c & 1) * TILE_B, ub + OFF_AL0 + (c & 1) * TILE_B,
                  ub + OFF_BH, ub + OFF_BL, m0, n0, lane);
        __syncthreads();
    }
    epi_act(acc, B1, sb, wid, lane, m0, n0);   // h1 -> A tiles
    __syncthreads();

    // ---- GEMM2: h1[128x128] @ W2 ----
    zero_acc(acc);
    for (int c = 0; c < 2; c++) {
        loadB(sb + OFF_BH, sb + OFF_BL, &g_W2t[0][0][0], &g_W2t[1][0][0], HDIM, c, tid);
        __syncthreads();
        mma_chunk(acc, ub + OFF_AH0 + c * TILE_B, ub + OFF_AL0 + c * TILE_B,
                  ub + OFF_BH, ub + OFF_BL, m0, n0, lane);
        __syncthreads();
    }
    epi_act(acc, B2, sb, wid, lane, m0, n0);   // h2 -> A tiles
    __syncthreads();

    // ---- GEMM3: h2[128x128] @ W3 -> scatter ----
    zero_acc(acc);
    for (int c = 0; c < 2; c++) {
        loadB(sb + OFF_BH, sb + OFF_BL, &g_W3t[0][0][0], &g_W3t[1][0][0], HDIM, c, tid);
        __syncthreads();
        mma_chunk(acc, ub + OFF_AH0 + c * TILE_B, ub + OFF_AL0 + c * TILE_B,
                  ub + OFF_BH, ub + OFF_BL, m0, n0, lane);
        __syncthreads();
    }
    epi_scatter(acc, B3, eidx, e0, lane, m0, n0);
}

// ---------------------------------------------------------------------------
// Node kernel (unchanged fp32)
// ---------------------------------------------------------------------------
__global__ void __launch_bounds__(256)
node_kernel(const float* __restrict__ hV,
            const float* __restrict__ n1g, const float* __restrict__ n1b,
            const float* __restrict__ D1,  const float* __restrict__ D1b,
            const float* __restrict__ D2,  const float* __restrict__ D2b,
            const float* __restrict__ n2g, const float* __restrict__ n2b,
            float* __restrict__ out)
{
    __shared__ float sX[32 * 128];
    __shared__ float sT[32 * 128];
    __shared__ float sW[32 * 128];

    const int tid  = threadIdx.x;
    const int lane = tid & 31;
    const int wid  = tid >> 5;
    const int n0   = blockIdx.x * 32;
    const int col  = 4 * lane;

    {
        float4 g1 = *(const float4*)(n1g + col);
        float4 b1 = *(const float4*)(n1b + col);
#pragma unroll
        for (int r = 0; r < 4; r++) {
            int row = wid + 8 * r;
            int n = n0 + row;
            float4 hv = *(const float4*)(hV + (size_t)n * HDIM + col);
            float4 dh = *(const float4*)(g_dh + (size_t)n * HDIM + col);
            float4 z;
            z.x = hv.x + dh.x; z.y = hv.y + dh.y; z.z = hv.z + dh.z; z.w = hv.w + dh.w;
            float s = z.x + z.y + z.z + z.w;
            float q = z.x * z.x + z.y * z.y + z.z * z.z + z.w * z.w;
#pragma unroll
            for (int o = 16; o > 0; o >>= 1) {
                s += __shfl_xor_sync(0xffffffffu, s, o);
                q += __shfl_xor_sync(0xffffffffu, q, o);
            }
            float m = s * (1.f / 128.f);
            float var = q * (1.f / 128.f) - m * m;
            float rstd = rsqrtf(var + 1e-5f);
            float4 x;
            x.x = (z.x - m) * rstd * g1.x + b1.x;
            x.y = (z.y - m) * rstd * g1.y + b1.y;
            x.z = (z.z - m) * rstd * g1.z + b1.z;
            x.w = (z.w - m) * rstd * g1.w + b1.w;
            *(float4*)(sX + row * HDIM + col) = x;
        }
    }
    __syncthreads();

    float acc2[4][4];
#pragma unroll
    for (int r = 0; r < 4; r++)
#pragma unroll
        for (int i = 0; i < 4; i++) acc2[r][i] = 0.f;

#pragma unroll 1
    for (int nc = 0; nc < 4; nc++) {
        float acc1[4][4];
#pragma unroll
        for (int r = 0; r < 4; r++)
#pragma unroll
            for (int i = 0; i < 4; i++) acc1[r][i] = 0.f;

#pragma unroll 1
        for (int kc = 0; kc < 4; kc++) {
#pragma unroll
            for (int i = 0; i < 4; i++) {
                int idx = tid + i * 256;
                int row = idx >> 5, c4 = idx & 31;
                ((float4*)sW)[idx] =
                    *(const float4*)(D1 + (size_t)(kc * 32 + row) * 512 + nc * 128 + 4 * c4);
            }
            __syncthreads();
#pragma unroll 8
            for (int k = 0; k < 32; k++) {
                float4 b = ((float4*)sW)[k * 32 + lane];
#pragma unroll
                for (int r = 0; r < 4; r++) {
                    float a = sX[(wid + 8 * r) * HDIM + kc * 32 + k];
                    acc1[r][0] += a * b.x; acc1[r][1] += a * b.y;
                    acc1[r][2] += a * b.z; acc1[r][3] += a * b.w;
                }
            }
            __syncthreads();
        }
        {
            float4 db = *(const float4*)(D1b + nc * 128 + col);
#pragma unroll
            for (int r = 0; r < 4; r++) {
                int row = wid + 8 * r;
                float4 t;
                t.x = gelu_f(acc1[r][0] + db.x);
                t.y = gelu_f(acc1[r][1] + db.y);
                t.z = gelu_f(acc1[r][2] + db.z);
                t.w = gelu_f(acc1[r][3] + db.w);
                *(float4*)(sT + row * HDIM + col) = t;
            }
        }
        __syncthreads();
#pragma unroll 1
        for (int kc = 0; kc < 4; kc++) {
#pragma unroll
            for (int i = 0; i < 4; i++) {
                int idx = tid + i * 256;
                int row = idx >> 5, c4 = idx & 31;
                ((float4*)sW)[idx] =
                    *(const float4*)(D2 + (size_t)(nc * 128 + kc * 32 + row) * 128 + 4 * c4);
            }
            __syncthreads();
#pragma unroll 8
            for (int k = 0; k < 32; k++) {
                float4 b = ((float4*)sW)[k * 32 + lane];
#pragma unroll
                for (int r = 0; r < 4; r++) {
                    float a = sT[(wid + 8 * r) * HDIM + kc * 32 + k];
                    acc2[r][0] += a * b.x; acc2[r][1] += a * b.y;
                    acc2[r][2] += a * b.z; acc2[r][3] += a * b.w;
                }
            }
            __syncthreads();
        }
    }

    {
        float4 g2  = *(const float4*)(n2g + col);
        float4 b2  = *(const float4*)(n2b + col);
        float4 db2 = *(const float4*)(D2b + col);
#pragma unroll
        for (int r = 0; r < 4; r++) {
            int row = wid + 8 * r;
            float4 x = *(float4*)(sX + row * HDIM + col);
            float4 z;
            z.x = x.x + acc2[r][0] + db2.x;
            z.y = x.y + acc2[r][1] + db2.y;
            z.z = x.z + acc2[r][2] + db2.z;
            z.w = x.w + acc2[r][3] + db2.w;
            float s = z.x + z.y + z.z + z.w;
            float q = z.x * z.x + z.y * z.y + z.z * z.z + z.w * z.w;
#pragma unroll
            for (int o = 16; o > 0; o >>= 1) {
                s += __shfl_xor_sync(0xffffffffu, s, o);
                q += __shfl_xor_sync(0xffffffffu, q, o);
            }
            float m = s * (1.f / 128.f);
            float var = q * (1.f / 128.f) - m * m;
            float rstd = rsqrtf(var + 1e-5f);
            float4 y;
            y.x = (z.x - m) * rstd * g2.x + b2.x;
            y.y = (z.y - m) * rstd * g2.y + b2.y;
            y.z = (z.z - m) * rstd * g2.z + b2.z;
            y.w = (z.w - m) * rstd * g2.w + b2.w;
            *(float4*)(out + (size_t)(n0 + row) * HDIM + col) = y;
        }
    }
}

extern "C" void kernel_launch(void* const* d_in, const int* in_sizes, int n_in,
                              void* d_out, int out_size)
{
    const float* hV  = (const float*)d_in[0];
    const float* hE  = (const float*)d_in[1];
    const int* eidx  = (const int*)d_in[2];
    const float* W1  = (const float*)d_in[3];
    const float* B1  = (const float*)d_in[4];
    const float* W2  = (const float*)d_in[5];
    const float* B2  = (const float*)d_in[6];
    const float* W3  = (const float*)d_in[7];
    const float* B3  = (const float*)d_in[8];
    const float* n1g = (const float*)d_in[9];
    const float* n1b = (const float*)d_in[10];
    const float* D1  = (const float*)d_in[11];
    const float* D1b = (const float*)d_in[12];
    const float* D2  = (const float*)d_in[13];
    const float* D2b = (const float*)d_in[14];
    const float* n2g = (const float*)d_in[15];
    const float* n2b = (const float*)d_in[16];
    float* out = (float*)d_out;

    cudaFuncSetAttribute(edge_mma_kernel,
                         cudaFuncAttributeMaxDynamicSharedMemorySize, EDGE_SMEM);

    zero_dh_kernel<<<(N_NODES * HDIM / 4) / 256, 256>>>();
    prep_weights<<<65536 / 256, 256>>>(W1, W2, W3);
    edge_mma_kernel<<<N_EDGES / 128, 256, EDGE_SMEM>>>(hE, eidx, B1, B2, B3);
    node_kernel<<<N_NODES / 32, 256>>>(hV, n1g, n1b, D1, D1b, D2, D2b, n2g, n2b, out);
}

// round 5
// speedup vs baseline: 1.6984x; 1.3660x over previous
#include <cuda_runtime.h>
#include <cuda_bf16.h>
#include <math.h>
#include <stdint.h>

#define N_NODES 20000
#define N_EDGES 320000
#define HDIM    128
#define INDIM   256

// ---------------- device scratch (no allocations allowed) ----------------
__device__ float g_dh[N_NODES * HDIM];
__device__ __align__(16) __nv_bfloat16 g_W1t[2][HDIM][INDIM];  // [hi/lo][n][k]
__device__ __align__(16) __nv_bfloat16 g_W2t[2][HDIM][HDIM];
__device__ __align__(16) __nv_bfloat16 g_W3t[2][HDIM][HDIM];

// ---------------- helpers ----------------
__device__ __forceinline__ float gelu_f(float x) { return x * normcdff(x); }

__device__ __forceinline__ uint32_t smem_u32(const void* p) {
    uint32_t a;
    asm("{ .reg .u64 t; cvta.to.shared.u64 t, %1; cvt.u32.u64 %0, t; }" : "=r"(a) : "l"(p));
    return a;
}

__device__ __forceinline__ void split_pair(float x0, float x1, uint32_t& hp, uint32_t& lp) {
    __nv_bfloat16 h0 = __float2bfloat16(x0), h1 = __float2bfloat16(x1);
    __nv_bfloat16 l0 = __float2bfloat16(x0 - __bfloat162float(h0));
    __nv_bfloat16 l1 = __float2bfloat16(x1 - __bfloat162float(h1));
    hp = (uint32_t)__bfloat16_as_ushort(h0) | ((uint32_t)__bfloat16_as_ushort(h1) << 16);
    lp = (uint32_t)__bfloat16_as_ushort(l0) | ((uint32_t)__bfloat16_as_ushort(l1) << 16);
}

__device__ __forceinline__ void red_add_v2(float* p, float x, float y) {
    asm volatile("red.global.add.v2.f32 [%0], {%1, %2};"
                 :: "l"(p), "f"(x), "f"(y) : "memory");
}

__device__ __forceinline__ void ldsm4(uint32_t addr, uint32_t r[4]) {
    asm volatile("ldmatrix.sync.aligned.m8n8.x4.shared.b16 {%0,%1,%2,%3}, [%4];"
                 : "=r"(r[0]), "=r"(r[1]), "=r"(r[2]), "=r"(r[3]) : "r"(addr));
}

__device__ __forceinline__ void mma16816(float c[4], const uint32_t a[4],
                                         uint32_t b0, uint32_t b1) {
    asm volatile("mma.sync.aligned.m16n8k16.row.col.f32.bf16.bf16.f32 "
                 "{%0,%1,%2,%3}, {%4,%5,%6,%7}, {%8,%9}, {%0,%1,%2,%3};"
                 : "+f"(c[0]), "+f"(c[1]), "+f"(c[2]), "+f"(c[3])
                 : "r"(a[0]), "r"(a[1]), "r"(a[2]), "r"(a[3]), "r"(b0), "r"(b1));
}

__device__ __forceinline__ void cp16(uint32_t dst, const void* src) {
    asm volatile("cp.async.cg.shared.global [%0], [%1], 16;" :: "r"(dst), "l"(src) : "memory");
}
#define CP_COMMIT() asm volatile("cp.async.commit_group;" ::: "memory")
#define CP_WAIT0()  asm volatile("cp.async.wait_group 0;" ::: "memory")

// XOR swizzle: 128-B rows, 16-B groups, group ^= (row & 7)
__device__ __forceinline__ uint32_t swoff(int row, int bytecol) {
    return (uint32_t)(row * 128 + (((bytecol >> 4) ^ (row & 7)) << 4) + (bytecol & 15));
}

// ---------------- misc kernels ----------------
__global__ void zero_dh_kernel() {
    int i = blockIdx.x * blockDim.x + threadIdx.x;
    ((float4*)g_dh)[i] = make_float4(0.f, 0.f, 0.f, 0.f);
}

// weights -> transposed [n][k] bf16 hi/lo planes
__global__ void prep_weights(const float* __restrict__ W1, const float* __restrict__ W2,
                             const float* __restrict__ W3) {
    int idx = blockIdx.x * 256 + threadIdx.x;
    float w; __nv_bfloat16 *ph, *pl;
    if (idx < 32768) {
        int n = idx >> 8, k = idx & 255;
        w = W1[k * HDIM + n];
        ph = &g_W1t[0][n][k]; pl = &g_W1t[1][n][k];
    } else if (idx < 49152) {
        int i = idx - 32768; int n = i >> 7, k = i & 127;
        w = W2[k * HDIM + n];
        ph = &g_W2t[0][n][k]; pl = &g_W2t[1][n][k];
    } else {
        int i = idx - 49152; int n = i >> 7, k = i & 127;
        w = W3[k * HDIM + n];
        ph = &g_W3t[0][n][k]; pl = &g_W3t[1][n][k];
    }
    __nv_bfloat16 h = __float2bfloat16(w);
    *ph = h;
    *pl = __float2bfloat16(w - __bfloat162float(h));
}

// ---------------- edge kernel (mma.sync bf16 hi/lo, swizzled, cp.async) ----
#define TILE16 16384
// layout: AH0 | AL0 | AH1 | AL1 | BH | BL  (each 16 KB; chunk c -> pair c)
#define OFF_A(c)  ((uint32_t)(c) * 2u * TILE16)
#define OFF_BH    (4u * TILE16)
#define OFF_BL    (5u * TILE16)
#define EDGE_SMEM (6 * TILE16)   // 98304 B

// split fp32 A chunk -> bf16 hi/lo swizzled tiles
static __device__ __forceinline__ void loadA_hE(char* sb, uint32_t abuf,
                                                const float* __restrict__ hE,
                                                int e0, int c, int tid) {
    char* th = sb + abuf;
    char* tl = th + TILE16;
#pragma unroll
    for (int it = 0; it < 8; it++) {
        int idx = tid + it * 256;            // 2048 float4 = 128 rows x 16
        int row = idx >> 4, c4 = idx & 15;
        float4 v = *(const float4*)(hE + (size_t)(e0 + row) * INDIM + c * 64 + c4 * 4);
        uint32_t h01, l01, h23, l23;
        split_pair(v.x, v.y, h01, l01);
        split_pair(v.z, v.w, h23, l23);
        uint32_t off = swoff(row, c4 * 8);
        *(uint2*)(th + off) = make_uint2(h01, h23);
        *(uint2*)(tl + off) = make_uint2(l01, l23);
    }
}

// cp.async B chunk (hi+lo planes), 16B per op, swizzled dst
static __device__ __forceinline__ void loadB_async(uint32_t ub,
                                                   const __nv_bfloat16* __restrict__ Wh,
                                                   const __nv_bfloat16* __restrict__ Wl,
                                                   int K, int c, int tid) {
#pragma unroll
    for (int it = 0; it < 4; it++) {
        int idx = tid + it * 256;            // 1024 x 16B = one plane
        int row = idx >> 3, g = idx & 7;
        uint32_t off = (uint32_t)(row * 128 + ((g ^ (row & 7)) << 4));
        cp16(ub + OFF_BH + off, Wh + (size_t)row * K + c * 64 + g * 8);
        cp16(ub + OFF_BL + off, Wl + (size_t)row * K + c * 64 + g * 8);
    }
    CP_COMMIT();
}

// one 64-K chunk: acc += Ah*Bh + Ah*Bl + Al*Bh  (B frags transient: low reg use)
static __device__ __forceinline__ void mma_chunk(float acc[2][8][4],
                                                 uint32_t Ah, uint32_t Al,
                                                 uint32_t Bh, uint32_t Bl,
                                                 int m0, int n0, int lane) {
    const int arow = lane & 15;
    const int agrp = lane >> 4;                           // +16B (k+8)
    const int brow = (lane & 7) + ((lane >> 4) & 1) * 8;
    const int bgrp = (lane >> 3) & 1;
#pragma unroll
    for (int ks = 0; ks < 4; ks++) {
        uint32_t ah[2][4], al[2][4];
#pragma unroll
        for (int mt = 0; mt < 2; mt++) {
            int r = m0 + mt * 16 + arow;
            uint32_t off = (uint32_t)(r * 128 + (((ks * 2 + agrp) ^ (r & 7)) << 4));
            ldsm4(Ah + off, ah[mt]);
            ldsm4(Al + off, al[mt]);
        }
#pragma unroll
        for (int np = 0; np < 4; np++) {
            int r = n0 + np * 16 + brow;
            uint32_t off = (uint32_t)(r * 128 + (((ks * 2 + bgrp) ^ (r & 7)) << 4));
            uint32_t rb[4];
            ldsm4(Bh + off, rb);
#pragma unroll
            for (int mt = 0; mt < 2; mt++) {
                mma16816(acc[mt][2 * np],     ah[mt], rb[0], rb[1]);
                mma16816(acc[mt][2 * np + 1], ah[mt], rb[2], rb[3]);
            }
#pragma unroll
            for (int mt = 0; mt < 2; mt++) {
                mma16816(acc[mt][2 * np],     al[mt], rb[0], rb[1]);
                mma16816(acc[mt][2 * np + 1], al[mt], rb[2], rb[3]);
            }
            ldsm4(Bl + off, rb);
#pragma unroll
            for (int mt = 0; mt < 2; mt++) {
                mma16816(acc[mt][2 * np],     ah[mt], rb[0], rb[1]);
                mma16816(acc[mt][2 * np + 1], ah[mt], rb[2], rb[3]);
            }
        }
    }
}

static __device__ __forceinline__ void zero_acc(float acc[2][8][4]) {
#pragma unroll
    for (int mt = 0; mt < 2; mt++)
#pragma unroll
        for (int nt = 0; nt < 8; nt++)
#pragma unroll
            for (int i = 0; i < 4; i++) acc[mt][nt][i] = 0.f;
}

// epilogue: gelu(acc + bias) -> bf16 hi/lo into A tile pair (wid>>2), swizzled
static __device__ __forceinline__ void epi_act(float acc[2][8][4], const float* __restrict__ bias,
                                               char* sb, int wid, int lane, int m0, int n0) {
    char* th = sb + OFF_A(wid >> 2);
    char* tl = th + TILE16;
    const int g = lane >> 2, t = lane & 3;
#pragma unroll
    for (int mt = 0; mt < 2; mt++) {
        int r0 = m0 + mt * 16 + g;
#pragma unroll
        for (int nt = 0; nt < 8; nt++) {
            int col = nt * 8 + 2 * t;                  // 0..63 within warp half
            float b0 = __ldg(&bias[n0 + col]);
            float b1 = __ldg(&bias[n0 + col + 1]);
            float x0 = gelu_f(acc[mt][nt][0] + b0);
            float x1 = gelu_f(acc[mt][nt][1] + b1);
            float x2 = gelu_f(acc[mt][nt][2] + b0);
            float x3 = gelu_f(acc[mt][nt][3] + b1);
            uint32_t hp, lp;
            split_pair(x0, x1, hp, lp);
            uint32_t off0 = swoff(r0, col * 2);
            *(uint32_t*)(th + off0) = hp;
            *(uint32_t*)(tl + off0) = lp;
            split_pair(x2, x3, hp, lp);
            uint32_t off1 = swoff(r0 + 8, col * 2);
            *(uint32_t*)(th + off1) = hp;
            *(uint32_t*)(tl + off1) = lp;
        }
    }
}

static __device__ __forceinline__ void epi_scatter(float acc[2][8][4], const float* __restrict__ bias,
                                                   const int* __restrict__ eidx, int e0,
                                                   int lane, int m0, int n0) {
    const int g = lane >> 2, t = lane & 3;
    const float inv = 1.0f / 30.0f;
#pragma unroll
    for (int mt = 0; mt < 2; mt++) {
        int r0 = m0 + mt * 16 + g;
        int s0 = eidx[e0 + r0];
        int s1 = eidx[e0 + r0 + 8];
        float* d0 = g_dh + (size_t)s0 * HDIM;
        float* d1 = g_dh + (size_t)s1 * HDIM;
#pragma unroll
        for (int nt = 0; nt < 8; nt++) {
            int col = n0 + nt * 8 + 2 * t;
            float b0 = __ldg(&bias[col]);
            float b1 = __ldg(&bias[col + 1]);
            red_add_v2(d0 + col, (acc[mt][nt][0] + b0) * inv, (acc[mt][nt][1] + b1) * inv);
            red_add_v2(d1 + col, (acc[mt][nt][2] + b0) * inv, (acc[mt][nt][3] + b1) * inv);
        }
    }
}

__global__ void __launch_bounds__(256, 2)
edge_mma_kernel(const float* __restrict__ hE, const int* __restrict__ eidx,
                const float* __restrict__ B1, const float* __restrict__ B2,
                const float* __restrict__ B3)
{
    extern __shared__ char sb[];
    const uint32_t ub = smem_u32(sb);

    const int tid = threadIdx.x, lane = tid & 31, wid = tid >> 5;
    const int m0 = (wid & 3) * 32;
    const int n0 = (wid >> 2) * 64;
    const int e0 = blockIdx.x * 128;

    float acc[2][8][4];
    zero_acc(acc);

    // ---- GEMM1: hE[128x256] @ W1 ----
    for (int c = 0; c < 4; c++) {
        loadB_async(ub, &g_W1t[0][0][0], &g_W1t[1][0][0], INDIM, c, tid);
        loadA_hE(sb, OFF_A(c & 1), hE, e0, c, tid);
        CP_WAIT0();
        __syncthreads();
        mma_chunk(acc, ub + OFF_A(c & 1), ub + OFF_A(c & 1) + TILE16,
                  ub + OFF_BH, ub + OFF_BL, m0, n0, lane);
        __syncthreads();
    }
    epi_act(acc, B1, sb, wid, lane, m0, n0);   // h1 -> A tiles
    __syncthreads();

    // ---- GEMM2: h1[128x128] @ W2 ----
    zero_acc(acc);
    for (int c = 0; c < 2; c++) {
        loadB_async(ub, &g_W2t[0][0][0], &g_W2t[1][0][0], HDIM, c, tid);
        CP_WAIT0();
        __syncthreads();
        mma_chunk(acc, ub + OFF_A(c), ub + OFF_A(c) + TILE16,
                  ub + OFF_BH, ub + OFF_BL, m0, n0, lane);
        __syncthreads();
    }
    epi_act(acc, B2, sb, wid, lane, m0, n0);   // h2 -> A tiles
    __syncthreads();

    // ---- GEMM3: h2[128x128] @ W3 -> scatter ----
    zero_acc(acc);
    for (int c = 0; c < 2; c++) {
        loadB_async(ub, &g_W3t[0][0][0], &g_W3t[1][0][0], HDIM, c, tid);
        CP_WAIT0();
        __syncthreads();
        mma_chunk(acc, ub + OFF_A(c), ub + OFF_A(c) + TILE16,
                  ub + OFF_BH, ub + OFF_BL, m0, n0, lane);
        __syncthreads();
    }
    epi_scatter(acc, B3, eidx, e0, lane, m0, n0);
}

// ---------------------------------------------------------------------------
// Node kernel (unchanged fp32)
// ---------------------------------------------------------------------------
__global__ void __launch_bounds__(256)
node_kernel(const float* __restrict__ hV,
            const float* __restrict__ n1g, const float* __restrict__ n1b,
            const float* __restrict__ D1,  const float* __restrict__ D1b,
            const float* __restrict__ D2,  const float* __restrict__ D2b,
            const float* __restrict__ n2g, const float* __restrict__ n2b,
            float* __restrict__ out)
{
    __shared__ float sX[32 * 128];
    __shared__ float sT[32 * 128];
    __shared__ float sW[32 * 128];

    const int tid  = threadIdx.x;
    const int lane = tid & 31;
    const int wid  = tid >> 5;
    const int n0   = blockIdx.x * 32;
    const int col  = 4 * lane;

    {
        float4 g1 = *(const float4*)(n1g + col);
        float4 b1 = *(const float4*)(n1b + col);
#pragma unroll
        for (int r = 0; r < 4; r++) {
            int row = wid + 8 * r;
            int n = n0 + row;
            float4 hv = *(const float4*)(hV + (size_t)n * HDIM + col);
            float4 dh = *(const float4*)(g_dh + (size_t)n * HDIM + col);
            float4 z;
            z.x = hv.x + dh.x; z.y = hv.y + dh.y; z.z = hv.z + dh.z; z.w = hv.w + dh.w;
            float s = z.x + z.y + z.z + z.w;
            float q = z.x * z.x + z.y * z.y + z.z * z.z + z.w * z.w;
#pragma unroll
            for (int o = 16; o > 0; o >>= 1) {
                s += __shfl_xor_sync(0xffffffffu, s, o);
                q += __shfl_xor_sync(0xffffffffu, q, o);
            }
            float m = s * (1.f / 128.f);
            float var = q * (1.f / 128.f) - m * m;
            float rstd = rsqrtf(var + 1e-5f);
            float4 x;
            x.x = (z.x - m) * rstd * g1.x + b1.x;
            x.y = (z.y - m) * rstd * g1.y + b1.y;
            x.z = (z.z - m) * rstd * g1.z + b1.z;
            x.w = (z.w - m) * rstd * g1.w + b1.w;
            *(float4*)(sX + row * HDIM + col) = x;
        }
    }
    __syncthreads();

    float acc2[4][4];
#pragma unroll
    for (int r = 0; r < 4; r++)
#pragma unroll
        for (int i = 0; i < 4; i++) acc2[r][i] = 0.f;

#pragma unroll 1
    for (int nc = 0; nc < 4; nc++) {
        float acc1[4][4];
#pragma unroll
        for (int r = 0; r < 4; r++)
#pragma unroll
            for (int i = 0; i < 4; i++) acc1[r][i] = 0.f;

#pragma unroll 1
        for (int kc = 0; kc < 4; kc++) {
#pragma unroll
            for (int i = 0; i < 4; i++) {
                int idx = tid + i * 256;
                int row = idx >> 5, c4 = idx & 31;
                ((float4*)sW)[idx] =
                    *(const float4*)(D1 + (size_t)(kc * 32 + row) * 512 + nc * 128 + 4 * c4);
            }
            __syncthreads();
#pragma unroll 8
            for (int k = 0; k < 32; k++) {
                float4 b = ((float4*)sW)[k * 32 + lane];
#pragma unroll
                for (int r = 0; r < 4; r++) {
                    float a = sX[(wid + 8 * r) * HDIM + kc * 32 + k];
                    acc1[r][0] += a * b.x; acc1[r][1] += a * b.y;
                    acc1[r][2] += a * b.z; acc1[r][3] += a * b.w;
                }
            }
            __syncthreads();
        }
        {
            float4 db = *(const float4*)(D1b + nc * 128 + col);
#pragma unroll
            for (int r = 0; r < 4; r++) {
                int row = wid + 8 * r;
                float4 t;
                t.x = gelu_f(acc1[r][0] + db.x);
                t.y = gelu_f(acc1[r][1] + db.y);
                t.z = gelu_f(acc1[r][2] + db.z);
                t.w = gelu_f(acc1[r][3] + db.w);
                *(float4*)(sT + row * HDIM + col) = t;
            }
        }
        __syncthreads();
#pragma unroll 1
        for (int kc = 0; kc < 4; kc++) {
#pragma unroll
            for (int i = 0; i < 4; i++) {
                int idx = tid + i * 256;
                int row = idx >> 5, c4 = idx & 31;
                ((float4*)sW)[idx] =
                    *(const float4*)(D2 + (size_t)(nc * 128 + kc * 32 + row) * 128 + 4 * c4);
            }
            __syncthreads();
#pragma unroll 8
            for (int k = 0; k < 32; k++) {
                float4 b = ((float4*)sW)[k * 32 + lane];
#pragma unroll
                for (int r = 0; r < 4; r++) {
                    float a = sT[(wid + 8 * r) * HDIM + kc * 32 + k];
                    acc2[r][0] += a * b.x; acc2[r][1] += a * b.y;
                    acc2[r][2] += a * b.z; acc2[r][3] += a * b.w;
                }
            }
            __syncthreads();
        }
    }

    {
        float4 g2  = *(const float4*)(n2g + col);
        float4 b2  = *(const float4*)(n2b + col);
        float4 db2 = *(const float4*)(D2b + col);
#pragma unroll
        for (int r = 0; r < 4; r++) {
            int row = wid + 8 * r;
            float4 x = *(float4*)(sX + row * HDIM + col);
            float4 z;
            z.x = x.x + acc2[r][0] + db2.x;
            z.y = x.y + acc2[r][1] + db2.y;
            z.z = x.z + acc2[r][2] + db2.z;
            z.w = x.w + acc2[r][3] + db2.w;
            float s = z.x + z.y + z.z + z.w;
            float q = z.x * z.x + z.y * z.y + z.z * z.z + z.w * z.w;
#pragma unroll
            for (int o = 16; o > 0; o >>= 1) {
                s += __shfl_xor_sync(0xffffffffu, s, o);
                q += __shfl_xor_sync(0xffffffffu, q, o);
            }
            float m = s * (1.f / 128.f);
            float var = q * (1.f / 128.f) - m * m;
            float rstd = rsqrtf(var + 1e-5f);
            float4 y;
            y.x = (z.x - m) * rstd * g2.x + b2.x;
            y.y = (z.y - m) * rstd * g2.y + b2.y;
            y.z = (z.z - m) * rstd * g2.z + b2.z;
            y.w = (z.w - m) * rstd * g2.w + b2.w;
            *(float4*)(out + (size_t)(n0 + row) * HDIM + col) = y;
        }
    }
}

extern "C" void kernel_launch(void* const* d_in, const int* in_sizes, int n_in,
                              void* d_out, int out_size)
{
    const float* hV  = (const float*)d_in[0];
    const float* hE  = (const float*)d_in[1];
    const int* eidx  = (const int*)d_in[2];
    const float* W1  = (const float*)d_in[3];
    const float* B1  = (const float*)d_in[4];
    const float* W2  = (const float*)d_in[5];
    const float* B2  = (const float*)d_in[6];
    const float* W3  = (const float*)d_in[7];
    const float* B3  = (const float*)d_in[8];
    const float* n1g = (const float*)d_in[9];
    const float* n1b = (const float*)d_in[10];
    const float* D1  = (const float*)d_in[11];
    const float* D1b = (const float*)d_in[12];
    const float* D2  = (const float*)d_in[13];
    const float* D2b = (const float*)d_in[14];
    const float* n2g = (const float*)d_in[15];
    const float* n2b = (const float*)d_in[16];
    float* out = (float*)d_out;

    cudaFuncSetAttribute(edge_mma_kernel,
                         cudaFuncAttributeMaxDynamicSharedMemorySize, EDGE_SMEM);

    zero_dh_kernel<<<(N_NODES * HDIM / 4) / 256, 256>>>();
    prep_weights<<<65536 / 256, 256>>>(W1, W2, W3);
    edge_mma_kernel<<<N_EDGES / 128, 256, EDGE_SMEM>>>(hE, eidx, B1, B2, B3);
    node_kernel<<<N_NODES / 32, 256>>>(hV, n1g, n1b, D1, D1b, D2, D2b, n2g, n2b, out);
}

// round 6
// speedup vs baseline: 1.8000x; 1.0598x over previous
#include <cuda_runtime.h>
#include <cuda_bf16.h>
#include <math.h>
#include <stdint.h>

#define N_NODES 20000
#define N_EDGES 320000
#define HDIM    128
#define INDIM   256

// ---------------- device scratch (no allocations allowed) ----------------
__device__ float g_dh[N_NODES * HDIM];
__device__ __align__(16) __nv_bfloat16 g_W1t[2][HDIM][INDIM];   // [hi/lo][n][k]
__device__ __align__(16) __nv_bfloat16 g_W2t[2][HDIM][HDIM];
__device__ __align__(16) __nv_bfloat16 g_W3t[2][HDIM][HDIM];
__device__ __align__(16) __nv_bfloat16 g_D1t[2][512][HDIM];     // [hi/lo][n][k]
__device__ __align__(16) __nv_bfloat16 g_D2t[2][HDIM][512];     // [hi/lo][n][k]

// ---------------- helpers ----------------
__device__ __forceinline__ float gelu_f(float x) { return x * normcdff(x); }

__device__ __forceinline__ uint32_t smem_u32(const void* p) {
    uint32_t a;
    asm("{ .reg .u64 t; cvta.to.shared.u64 t, %1; cvt.u32.u64 %0, t; }" : "=r"(a) : "l"(p));
    return a;
}

__device__ __forceinline__ void split_pair(float x0, float x1, uint32_t& hp, uint32_t& lp) {
    __nv_bfloat16 h0 = __float2bfloat16(x0), h1 = __float2bfloat16(x1);
    __nv_bfloat16 l0 = __float2bfloat16(x0 - __bfloat162float(h0));
    __nv_bfloat16 l1 = __float2bfloat16(x1 - __bfloat162float(h1));
    hp = (uint32_t)__bfloat16_as_ushort(h0) | ((uint32_t)__bfloat16_as_ushort(h1) << 16);
    lp = (uint32_t)__bfloat16_as_ushort(l0) | ((uint32_t)__bfloat16_as_ushort(l1) << 16);
}

__device__ __forceinline__ void red_add_v2(float* p, float x, float y) {
    asm volatile("red.global.add.v2.f32 [%0], {%1, %2};"
                 :: "l"(p), "f"(x), "f"(y) : "memory");
}

__device__ __forceinline__ void ldsm4(uint32_t addr, uint32_t r[4]) {
    asm volatile("ldmatrix.sync.aligned.m8n8.x4.shared.b16 {%0,%1,%2,%3}, [%4];"
                 : "=r"(r[0]), "=r"(r[1]), "=r"(r[2]), "=r"(r[3]) : "r"(addr));
}

__device__ __forceinline__ void mma16816(float c[4], const uint32_t a[4],
                                         uint32_t b0, uint32_t b1) {
    asm volatile("mma.sync.aligned.m16n8k16.row.col.f32.bf16.bf16.f32 "
                 "{%0,%1,%2,%3}, {%4,%5,%6,%7}, {%8,%9}, {%0,%1,%2,%3};"
                 : "+f"(c[0]), "+f"(c[1]), "+f"(c[2]), "+f"(c[3])
                 : "r"(a[0]), "r"(a[1]), "r"(a[2]), "r"(a[3]), "r"(b0), "r"(b1));
}

__device__ __forceinline__ void cp16(uint32_t dst, const void* src) {
    asm volatile("cp.async.cg.shared.global [%0], [%1], 16;" :: "r"(dst), "l"(src) : "memory");
}
#define CP_COMMIT() asm volatile("cp.async.commit_group;" ::: "memory")
#define CP_WAIT0()  asm volatile("cp.async.wait_group 0;" ::: "memory")

// XOR swizzle: 128-B rows, 16-B groups, group ^= (row & 7)
__device__ __forceinline__ uint32_t swoff(int row, int bytecol) {
    return (uint32_t)(row * 128 + (((bytecol >> 4) ^ (row & 7)) << 4) + (bytecol & 15));
}

#define TILE16 16384

// ---------------- misc kernels ----------------
__global__ void zero_dh_kernel() {
    int i = blockIdx.x * blockDim.x + threadIdx.x;
    ((float4*)g_dh)[i] = make_float4(0.f, 0.f, 0.f, 0.f);
}

// weights -> transposed [n][k] bf16 hi/lo planes.
// ranges: W1 32768 | W2 16384 | W3 16384 | D1 65536 | D2 65536 = 196608
__global__ void prep_weights(const float* __restrict__ W1, const float* __restrict__ W2,
                             const float* __restrict__ W3, const float* __restrict__ D1,
                             const float* __restrict__ D2) {
    int idx = blockIdx.x * 256 + threadIdx.x;
    float w; __nv_bfloat16 *ph, *pl;
    if (idx < 32768) {
        int n = idx >> 8, k = idx & 255;
        w = W1[k * HDIM + n];
        ph = &g_W1t[0][n][k]; pl = &g_W1t[1][n][k];
    } else if (idx < 49152) {
        int i = idx - 32768; int n = i >> 7, k = i & 127;
        w = W2[k * HDIM + n];
        ph = &g_W2t[0][n][k]; pl = &g_W2t[1][n][k];
    } else if (idx < 65536) {
        int i = idx - 49152; int n = i >> 7, k = i & 127;
        w = W3[k * HDIM + n];
        ph = &g_W3t[0][n][k]; pl = &g_W3t[1][n][k];
    } else if (idx < 131072) {
        int i = idx - 65536; int n = i >> 7, k = i & 127;   // n<512, k<128
        w = D1[k * 512 + n];
        ph = &g_D1t[0][n][k]; pl = &g_D1t[1][n][k];
    } else {
        int i = idx - 131072; int n = i >> 9, k = i & 511;  // n<128, k<512
        w = D2[k * HDIM + n];
        ph = &g_D2t[0][n][k]; pl = &g_D2t[1][n][k];
    }
    __nv_bfloat16 h = __float2bfloat16(w);
    *ph = h;
    *pl = __float2bfloat16(w - __bfloat162float(h));
}

// ---------------- shared GEMM pieces ----------------
// cp.async one B chunk (hi+lo planes, 128 rows x 64 k bf16 each), swizzled dst
static __device__ __forceinline__ void loadB_async(uint32_t bh, uint32_t bl,
                                                   const __nv_bfloat16* __restrict__ Wh,
                                                   const __nv_bfloat16* __restrict__ Wl,
                                                   int K, int c, int tid) {
#pragma unroll
    for (int it = 0; it < 4; it++) {
        int idx = tid + it * 256;
        int row = idx >> 3, g = idx & 7;
        uint32_t off = (uint32_t)(row * 128 + ((g ^ (row & 7)) << 4));
        cp16(bh + off, Wh + (size_t)row * K + c * 64 + g * 8);
        cp16(bl + off, Wl + (size_t)row * K + c * 64 + g * 8);
    }
    CP_COMMIT();
}

// one 64-K chunk: acc += Ah*Bh + Ah*Bl + Al*Bh
static __device__ __forceinline__ void mma_chunk(float acc[2][8][4],
                                                 uint32_t Ah, uint32_t Al,
                                                 uint32_t Bh, uint32_t Bl,
                                                 int m0, int n0, int lane) {
    const int arow = lane & 15;
    const int agrp = lane >> 4;
    const int brow = (lane & 7) + ((lane >> 4) & 1) * 8;
    const int bgrp = (lane >> 3) & 1;
#pragma unroll
    for (int ks = 0; ks < 4; ks++) {
        uint32_t ah[2][4], al[2][4];
#pragma unroll
        for (int mt = 0; mt < 2; mt++) {
            int r = m0 + mt * 16 + arow;
            uint32_t off = (uint32_t)(r * 128 + (((ks * 2 + agrp) ^ (r & 7)) << 4));
            ldsm4(Ah + off, ah[mt]);
            ldsm4(Al + off, al[mt]);
        }
#pragma unroll
        for (int np = 0; np < 4; np++) {
            int r = n0 + np * 16 + brow;
            uint32_t off = (uint32_t)(r * 128 + (((ks * 2 + bgrp) ^ (r & 7)) << 4));
            uint32_t rb[4];
            ldsm4(Bh + off, rb);
#pragma unroll
            for (int mt = 0; mt < 2; mt++) {
                mma16816(acc[mt][2 * np],     ah[mt], rb[0], rb[1]);
                mma16816(acc[mt][2 * np + 1], ah[mt], rb[2], rb[3]);
            }
#pragma unroll
            for (int mt = 0; mt < 2; mt++) {
                mma16816(acc[mt][2 * np],     al[mt], rb[0], rb[1]);
                mma16816(acc[mt][2 * np + 1], al[mt], rb[2], rb[3]);
            }
            ldsm4(Bl + off, rb);
#pragma unroll
            for (int mt = 0; mt < 2; mt++) {
                mma16816(acc[mt][2 * np],     ah[mt], rb[0], rb[1]);
                mma16816(acc[mt][2 * np + 1], ah[mt], rb[2], rb[3]);
            }
        }
    }
}

static __device__ __forceinline__ void zero_acc(float acc[2][8][4]) {
#pragma unroll
    for (int mt = 0; mt < 2; mt++)
#pragma unroll
        for (int nt = 0; nt < 8; nt++)
#pragma unroll
            for (int i = 0; i < 4; i++) acc[mt][nt][i] = 0.f;
}

// epilogue: gelu(acc + bias[n0+col]) -> bf16 hi/lo into tile pair (wid>>2) at tbase
static __device__ __forceinline__ void epi_act(float acc[2][8][4], const float* __restrict__ bias,
                                               char* tbase, int wid, int lane, int m0, int n0) {
    char* th = tbase + (uint32_t)(wid >> 2) * 2u * TILE16;
    char* tl = th + TILE16;
    const int g = lane >> 2, t = lane & 3;
#pragma unroll
    for (int mt = 0; mt < 2; mt++) {
        int r0 = m0 + mt * 16 + g;
#pragma unroll
        for (int nt = 0; nt < 8; nt++) {
            int col = nt * 8 + 2 * t;
            float b0 = __ldg(&bias[n0 + col]);
            float b1 = __ldg(&bias[n0 + col + 1]);
            float x0 = gelu_f(acc[mt][nt][0] + b0);
            float x1 = gelu_f(acc[mt][nt][1] + b1);
            float x2 = gelu_f(acc[mt][nt][2] + b0);
            float x3 = gelu_f(acc[mt][nt][3] + b1);
            uint32_t hp, lp;
            split_pair(x0, x1, hp, lp);
            uint32_t off0 = swoff(r0, col * 2);
            *(uint32_t*)(th + off0) = hp;
            *(uint32_t*)(tl + off0) = lp;
            split_pair(x2, x3, hp, lp);
            uint32_t off1 = swoff(r0 + 8, col * 2);
            *(uint32_t*)(th + off1) = hp;
            *(uint32_t*)(tl + off1) = lp;
        }
    }
}

// ---------------- edge kernel ----------------
// layout: AH0 | AL0 | AH1 | AL1 | BH | BL  (each 16 KB)
#define OFF_A(c)  ((uint32_t)(c) * 2u * TILE16)
#define OFF_BH    (4u * TILE16)
#define OFF_BL    (5u * TILE16)
#define EDGE_SMEM (6 * TILE16)   // 98304 B

static __device__ __forceinline__ void loadA_hE(char* sb, uint32_t abuf,
                                                const float* __restrict__ hE,
                                                int e0, int c, int tid) {
    char* th = sb + abuf;
    char* tl = th + TILE16;
#pragma unroll
    for (int it = 0; it < 8; it++) {
        int idx = tid + it * 256;
        int row = idx >> 4, c4 = idx & 15;
        float4 v = *(const float4*)(hE + (size_t)(e0 + row) * INDIM + c * 64 + c4 * 4);
        uint32_t h01, l01, h23, l23;
        split_pair(v.x, v.y, h01, l01);
        split_pair(v.z, v.w, h23, l23);
        uint32_t off = swoff(row, c4 * 8);
        *(uint2*)(th + off) = make_uint2(h01, h23);
        *(uint2*)(tl + off) = make_uint2(l01, l23);
    }
}

static __device__ __forceinline__ void epi_scatter(float acc[2][8][4], const float* __restrict__ bias,
                                                   const int* __restrict__ eidx, int e0,
                                                   int lane, int m0, int n0) {
    const int g = lane >> 2, t = lane & 3;
    const float inv = 1.0f / 30.0f;
#pragma unroll
    for (int mt = 0; mt < 2; mt++) {
        int r0 = m0 + mt * 16 + g;
        int s0 = eidx[e0 + r0];
        int s1 = eidx[e0 + r0 + 8];
        float* d0 = g_dh + (size_t)s0 * HDIM;
        float* d1 = g_dh + (size_t)s1 * HDIM;
#pragma unroll
        for (int nt = 0; nt < 8; nt++) {
            int col = n0 + nt * 8 + 2 * t;
            float b0 = __ldg(&bias[col]);
            float b1 = __ldg(&bias[col + 1]);
            red_add_v2(d0 + col, (acc[mt][nt][0] + b0) * inv, (acc[mt][nt][1] + b1) * inv);
            red_add_v2(d1 + col, (acc[mt][nt][2] + b0) * inv, (acc[mt][nt][3] + b1) * inv);
        }
    }
}

__global__ void __launch_bounds__(256, 2)
edge_mma_kernel(const float* __restrict__ hE, const int* __restrict__ eidx,
                const float* __restrict__ B1, const float* __restrict__ B2,
                const float* __restrict__ B3)
{
    extern __shared__ char sb[];
    const uint32_t ub = smem_u32(sb);

    const int tid = threadIdx.x, lane = tid & 31, wid = tid >> 5;
    const int m0 = (wid & 3) * 32;
    const int n0 = (wid >> 2) * 64;
    const int e0 = blockIdx.x * 128;

    float acc[2][8][4];
    zero_acc(acc);

    // ---- GEMM1: hE[128x256] @ W1 ----
    loadB_async(ub + OFF_BH, ub + OFF_BL, &g_W1t[0][0][0], &g_W1t[1][0][0], INDIM, 0, tid);
    loadA_hE(sb, OFF_A(0), hE, e0, 0, tid);
    CP_WAIT0();
    __syncthreads();
    for (int c = 0; c < 4; c++) {
        mma_chunk(acc, ub + OFF_A(c & 1), ub + OFF_A(c & 1) + TILE16,
                  ub + OFF_BH, ub + OFF_BL, m0, n0, lane);
        if (c < 3) loadA_hE(sb, OFF_A((c + 1) & 1), hE, e0, c + 1, tid);  // overlaps tensor drain
        __syncthreads();
        if (c < 3) {
            loadB_async(ub + OFF_BH, ub + OFF_BL, &g_W1t[0][0][0], &g_W1t[1][0][0], INDIM, c + 1, tid);
            CP_WAIT0();
            __syncthreads();
        }
    }
    epi_act(acc, B1, sb, wid, lane, m0, n0);   // h1 -> A tiles
    __syncthreads();

    // ---- GEMM2: h1[128x128] @ W2 ----
    zero_acc(acc);
    loadB_async(ub + OFF_BH, ub + OFF_BL, &g_W2t[0][0][0], &g_W2t[1][0][0], HDIM, 0, tid);
    CP_WAIT0();
    __syncthreads();
    for (int c = 0; c < 2; c++) {
        mma_chunk(acc, ub + OFF_A(c), ub + OFF_A(c) + TILE16,
                  ub + OFF_BH, ub + OFF_BL, m0, n0, lane);
        __syncthreads();
        if (c == 0) {
            loadB_async(ub + OFF_BH, ub + OFF_BL, &g_W2t[0][0][0], &g_W2t[1][0][0], HDIM, 1, tid);
            CP_WAIT0();
            __syncthreads();
        }
    }
    epi_act(acc, B2, sb, wid, lane, m0, n0);   // h2 -> A tiles
    __syncthreads();

    // ---- GEMM3: h2[128x128] @ W3 -> scatter ----
    zero_acc(acc);
    loadB_async(ub + OFF_BH, ub + OFF_BL, &g_W3t[0][0][0], &g_W3t[1][0][0], HDIM, 0, tid);
    CP_WAIT0();
    __syncthreads();
    for (int c = 0; c < 2; c++) {
        mma_chunk(acc, ub + OFF_A(c), ub + OFF_A(c) + TILE16,
                  ub + OFF_BH, ub + OFF_BL, m0, n0, lane);
        __syncthreads();
        if (c == 0) {
            loadB_async(ub + OFF_BH, ub + OFF_BL, &g_W3t[0][0][0], &g_W3t[1][0][0], HDIM, 1, tid);
            CP_WAIT0();
            __syncthreads();
        }
    }
    epi_scatter(acc, B3, eidx, e0, lane, m0, n0);
}

// ---------------- node kernel (mma, 128 nodes/CTA, double-buffered B) ------
// layout: X(4 tiles) | T(4 tiles, reused as fp32 z) | B0(2) | B1(2) = 12 tiles
#define NOFF_X(c) ((uint32_t)(c) * 2u * TILE16)
#define NOFF_T(c) ((uint32_t)(4 + 2 * (c)) * TILE16)
#define NOFF_B(b) ((uint32_t)(8 + 2 * (b)) * TILE16)
#define NODE_SMEM (12 * TILE16)   // 196608 B

// step 0..15: nc = step>>2; r = step&3; r<2 -> D1 chunk (nc, r); else D2 chunk (nc*2 + r-2)
static __device__ __forceinline__ void node_loadB(uint32_t bh, int step, int tid) {
    int nc = step >> 2, r = step & 3;
    if (r < 2)
        loadB_async(bh, bh + TILE16, &g_D1t[0][nc * 128][0], &g_D1t[1][nc * 128][0], 128, r, tid);
    else
        loadB_async(bh, bh + TILE16, &g_D2t[0][0][0], &g_D2t[1][0][0], 512, nc * 2 + (r - 2), tid);
}

static __device__ __forceinline__ float xrec(char* sb, int r, int c) {
    char* th = sb + NOFF_X(c >> 6);
    uint32_t off = swoff(r, (c & 63) * 2);
    float hi = __bfloat162float(*(__nv_bfloat16*)(th + off));
    float lo = __bfloat162float(*(__nv_bfloat16*)(th + off + TILE16));
    return hi + lo;
}

__global__ void __launch_bounds__(256, 1)
node_mma_kernel(const float* __restrict__ hV,
                const float* __restrict__ n1g, const float* __restrict__ n1b,
                const float* __restrict__ D1b, const float* __restrict__ D2b,
                const float* __restrict__ n2g, const float* __restrict__ n2b,
                float* __restrict__ out)
{
    extern __shared__ char sb[];
    const uint32_t ub = smem_u32(sb);

    const int tid = threadIdx.x, lane = tid & 31, wid = tid >> 5;
    const int m0 = (wid & 3) * 32;
    const int n0 = (wid >> 2) * 64;
    const int v0 = blockIdx.x * 128;
    const int col4 = 4 * lane;

    // ---- LN1(h_V + dh) -> X bf16 hi/lo tiles ----
    {
        float4 g1 = *(const float4*)(n1g + col4);
        float4 b1 = *(const float4*)(n1b + col4);
        char* th = sb + NOFF_X(col4 >> 6);
        char* tl = th + TILE16;
        const int bc = (col4 & 63) * 2;
#pragma unroll 4
        for (int rr = 0; rr < 16; rr++) {
            int row = wid * 16 + rr;
            int n = v0 + row; if (n >= N_NODES) n = N_NODES - 1;
            float4 hv = *(const float4*)(hV + (size_t)n * HDIM + col4);
            float4 dh = *(const float4*)(g_dh + (size_t)n * HDIM + col4);
            float4 z;
            z.x = hv.x + dh.x; z.y = hv.y + dh.y; z.z = hv.z + dh.z; z.w = hv.w + dh.w;
            float s = z.x + z.y + z.z + z.w;
            float q = z.x * z.x + z.y * z.y + z.z * z.z + z.w * z.w;
#pragma unroll
            for (int o = 16; o > 0; o >>= 1) {
                s += __shfl_xor_sync(0xffffffffu, s, o);
                q += __shfl_xor_sync(0xffffffffu, q, o);
            }
            float m = s * (1.f / 128.f);
            float var = q * (1.f / 128.f) - m * m;
            float rstd = rsqrtf(var + 1e-5f);
            float4 x;
            x.x = (z.x - m) * rstd * g1.x + b1.x;
            x.y = (z.y - m) * rstd * g1.y + b1.y;
            x.z = (z.z - m) * rstd * g1.z + b1.z;
            x.w = (z.w - m) * rstd * g1.w + b1.w;
            uint32_t hp, lp;
            split_pair(x.x, x.y, hp, lp);
            uint32_t o0 = swoff(row, bc);
            *(uint32_t*)(th + o0) = hp;
            *(uint32_t*)(tl + o0) = lp;
            split_pair(x.z, x.w, hp, lp);
            uint32_t o1 = swoff(row, bc + 4);
            *(uint32_t*)(th + o1) = hp;
            *(uint32_t*)(tl + o1) = lp;
        }
    }
    node_loadB(ub + NOFF_B(0), 0, tid);
    __syncthreads();

    // ---- FFN: acc2 = gelu(X @ D1 + D1b) @ D2 over 4 N-chunks ----
    float acc2[2][8][4];
    zero_acc(acc2);
    int step = 0;
#pragma unroll 1
    for (int nc = 0; nc < 4; nc++) {
        float acc1[2][8][4];
        zero_acc(acc1);
#pragma unroll 1
        for (int kc = 0; kc < 2; kc++, step++) {
            CP_WAIT0();
            __syncthreads();
            if (step < 15) node_loadB(ub + NOFF_B((step + 1) & 1), step + 1, tid);
            uint32_t b = ub + NOFF_B(step & 1);
            mma_chunk(acc1, ub + NOFF_X(kc), ub + NOFF_X(kc) + TILE16, b, b + TILE16, m0, n0, lane);
            __syncthreads();
        }
        epi_act(acc1, D1b + nc * 128, sb + NOFF_T(0), wid, lane, m0, n0);
        __syncthreads();
#pragma unroll 1
        for (int kc = 0; kc < 2; kc++, step++) {
            CP_WAIT0();
            __syncthreads();
            if (step < 15) node_loadB(ub + NOFF_B((step + 1) & 1), step + 1, tid);
            uint32_t b = ub + NOFF_B(step & 1);
            mma_chunk(acc2, ub + NOFF_T(kc), ub + NOFF_T(kc) + TILE16, b, b + TILE16, m0, n0, lane);
            __syncthreads();
        }
    }

    // ---- z = x + dh2 + D2b -> fp32 into T region ----
    float* zbuf = (float*)(sb + NOFF_T(0));
    {
        const int g = lane >> 2, t = lane & 3;
#pragma unroll
        for (int mt = 0; mt < 2; mt++) {
            int r0 = m0 + mt * 16 + g;
#pragma unroll
            for (int nt = 0; nt < 8; nt++) {
                int c0 = n0 + nt * 8 + 2 * t;
                float d0 = __ldg(D2b + c0), d1 = __ldg(D2b + c0 + 1);
                zbuf[r0 * 128 + c0]           = xrec(sb, r0, c0)     + acc2[mt][nt][0] + d0;
                zbuf[r0 * 128 + c0 + 1]       = xrec(sb, r0, c0 + 1) + acc2[mt][nt][1] + d1;
                zbuf[(r0 + 8) * 128 + c0]     = xrec(sb, r0 + 8, c0)     + acc2[mt][nt][2] + d0;
                zbuf[(r0 + 8) * 128 + c0 + 1] = xrec(sb, r0 + 8, c0 + 1) + acc2[mt][nt][3] + d1;
            }
        }
    }
    __syncthreads();

    // ---- LN2 -> out ----
    {
        float4 g2 = *(const float4*)(n2g + col4);
        float4 b2 = *(const float4*)(n2b + col4);
#pragma unroll 4
        for (int rr = 0; rr < 16; rr++) {
            int row = wid * 16 + rr;
            int n = v0 + row;
            float4 z = *(float4*)(zbuf + row * 128 + col4);
            float s = z.x + z.y + z.z + z.w;
            float q = z.x * z.x + z.y * z.y + z.z * z.z + z.w * z.w;
#pragma unroll
            for (int o = 16; o > 0; o >>= 1) {
                s += __shfl_xor_sync(0xffffffffu, s, o);
                q += __shfl_xor_sync(0xffffffffu, q, o);
            }
            float m = s * (1.f / 128.f);
            float var = q * (1.f / 128.f) - m * m;
            float rstd = rsqrtf(var + 1e-5f);
            if (n < N_NODES) {
                float4 y;
                y.x = (z.x - m) * rstd * g2.x + b2.x;
                y.y = (z.y - m) * rstd * g2.y + b2.y;
                y.z = (z.z - m) * rstd * g2.z + b2.z;
                y.w = (z.w - m) * rstd * g2.w + b2.w;
                *(float4*)(out + (size_t)n * HDIM + col4) = y;
            }
        }
    }
}

extern "C" void kernel_launch(void* const* d_in, const int* in_sizes, int n_in,
                              void* d_out, int out_size)
{
    const float* hV  = (const float*)d_in[0];
    const float* hE  = (const float*)d_in[1];
    const int* eidx  = (const int*)d_in[2];
    const float* W1  = (const float*)d_in[3];
    const float* B1  = (const float*)d_in[4];
    const float* W2  = (const float*)d_in[5];
    const float* B2  = (const float*)d_in[6];
    const float* W3  = (const float*)d_in[7];
    const float* B3  = (const float*)d_in[8];
    const float* n1g = (const float*)d_in[9];
    const float* n1b = (const float*)d_in[10];
    const float* D1  = (const float*)d_in[11];
    const float* D1b = (const float*)d_in[12];
    const float* D2  = (const float*)d_in[13];
    const float* D2b = (const float*)d_in[14];
    const float* n2g = (const float*)d_in[15];
    const float* n2b = (const float*)d_in[16];
    float* out = (float*)d_out;

    cudaFuncSetAttribute(edge_mma_kernel,
                         cudaFuncAttributeMaxDynamicSharedMemorySize, EDGE_SMEM);
    cudaFuncSetAttribute(node_mma_kernel,
                         cudaFuncAttributeMaxDynamicSharedMemorySize, NODE_SMEM);

    zero_dh_kernel<<<(N_NODES * HDIM / 4) / 256, 256>>>();
    prep_weights<<<196608 / 256, 256>>>(W1, W2, W3, D1, D2);
    edge_mma_kernel<<<N_EDGES / 128, 256, EDGE_SMEM>>>(hE, eidx, B1, B2, B3);
    node_mma_kernel<<<(N_NODES + 127) / 128, 256, NODE_SMEM>>>(
        hV, n1g, n1b, D1b, D2b, n2g, n2b, out);
}